// round 11
// baseline (speedup 1.0000x reference)
#include <cuda_runtime.h>

// CapsuleConvTranspose2d (2,64,32,32) -> (2,64,64,64): stride-2 3x3 transposed
// conv into 8 out-capsules x 8 dims, 3-iter k-means routing, squash, bias.
// SINGLE fused kernel (no prep): each block stages its x slice and packed
// weight slabs in shared memory.
//
// patch[n,c,kh,kw,p,q] = x[n,c,(p+kh-1)/2,(q+kw-1)/2] iff (p+kh-1) even & in
// range, else 0. Valid kh depends only on parity of p (even->{1}, odd->{0,2});
// same for q/kw. Border taps (p or q = 63, tap 2) zero-filled: a zero prior
// routes identically (exp(0)=1 in Z), counted in NZEROS.
//
// Routing algebra: iterations only consume out/||out||, and out = acc/Z, so Z
// cancels in iterations 0..1 (and the init's 1/72). Z is computed only in the
// final iteration where the magnitude feeds squash. Softmax without max
// subtraction (logits O(1), fp32-safe); zero priors add exactly NZEROS to Z.
//
// Vector math is packed f32x2 (SASS FFMA2 via PTX fma.rn.f32x2); width-8
// cross-lane reductions use packed reduce-scatter (7 wavefronts) + all-gather.
//
// Block = 512 threads = one (n, p) row x 8 consecutive q. Group gi = tid>>6
// owns pixel q0+gi; group parity = q parity -> class is warp-uniform.
//   x smem layout: [a*610 + f0*76 + l*8 + jj]  (a = kh slot, f0 = field,
//   l = in-dim, jj = j - j0). Bank-distinct for all 4 classes (verified).
//   weight slabs: packed [( (l*8+g)*ntap + tp )*8 + m], classes A (q even)
//   and B (q odd), staged from wt with flipped taps baked in.

typedef unsigned long long ull;

__device__ __forceinline__ ull pack2(float lo, float hi) {
    ull r; asm("mov.b64 %0,{%1,%2};" : "=l"(r) : "f"(lo), "f"(hi)); return r;
}
__device__ __forceinline__ void unpack2(ull v, float& lo, float& hi) {
    asm("mov.b64 {%0,%1},%2;" : "=f"(lo), "=f"(hi) : "l"(v));
}
__device__ __forceinline__ ull fma2(ull a, ull b, ull c) {
    ull d; asm("fma.rn.f32x2 %0,%1,%2,%3;" : "=l"(d) : "l"(a), "l"(b), "l"(c)); return d;
}
__device__ __forceinline__ ull mul2(ull a, ull b) {
    ull d; asm("mul.rn.f32x2 %0,%1,%2;" : "=l"(d) : "l"(a), "l"(b)); return d;
}
__device__ __forceinline__ ull add2(ull a, ull b) {
    ull d; asm("add.rn.f32x2 %0,%1,%2;" : "=l"(d) : "l"(a), "l"(b)); return d;
}

// packed reduce-scatter over width 8 -> fully-summed component r on lane r
__device__ __forceinline__ float rs8p(const ull v[4], int r)
{
    const unsigned FULL = 0xffffffffu;
    const bool b4 = (r & 4) != 0, b2 = (r & 2) != 0, b1 = (r & 1) != 0;
    ull s0 = b4 ? v[0] : v[2];
    ull s1 = b4 ? v[1] : v[3];
    ull k0 = b4 ? v[2] : v[0];
    ull k1 = b4 ? v[3] : v[1];
    ull w0 = add2(k0, __shfl_xor_sync(FULL, s0, 4, 8));
    ull w1 = add2(k1, __shfl_xor_sync(FULL, s1, 4, 8));
    ull su = b2 ? w0 : w1;
    ull ku = b2 ? w1 : w0;
    ull u  = add2(ku, __shfl_xor_sync(FULL, su, 2, 8));
    float ua, ub; unpack2(u, ua, ub);
    float sf = b1 ? ua : ub;
    float kf = b1 ? ub : ua;
    return kf + __shfl_xor_sync(FULL, sf, 1, 8);
}

// all-gather over width 8: scalar s (component r on lane r) -> o2[4] packed
__device__ __forceinline__ void ag8p(float s, int r, ull o2[4])
{
    const unsigned FULL = 0xffffffffu;
    const bool b4 = (r & 4) != 0, b2 = (r & 2) != 0, b1 = (r & 1) != 0;
    float t = __shfl_xor_sync(FULL, s, 1, 8);
    float lo = b1 ? t : s;
    float hi = b1 ? s : t;
    ull u  = pack2(lo, hi);
    ull t2 = __shfl_xor_sync(FULL, u, 2, 8);
    ull w0 = b2 ? t2 : u;
    ull w1 = b2 ? u : t2;
    ull t0 = __shfl_xor_sync(FULL, w0, 4, 8);
    ull t1 = __shfl_xor_sync(FULL, w1, 4, 8);
    o2[0] = b4 ? t0 : w0;
    o2[1] = b4 ? t1 : w1;
    o2[2] = b4 ? w0 : t0;
    o2[3] = b4 ? w1 : t1;
}

// routing + squash + store; priors packed: pri2[k][j] = (m=2j, m=2j+1)
template<int CNT>
__device__ __forceinline__ void route_and_store(
    ull pri2[CNT][4], int n, int p, int q, int ch, int r,
    const float* __restrict__ bs, float* __restrict__ y)
{
    constexpr float NZEROS = (float)(72 - 8 * CNT);
    const unsigned FULL = 0xffffffffu;

    // init: out0 direction = sum of priors (1/72 cancels)
    ull o2[4];
    #pragma unroll
    for (int j = 0; j < 4; j++) o2[j] = pri2[0][j];
    #pragma unroll
    for (int k = 1; k < CNT; k++)
        #pragma unroll
        for (int j = 0; j < 4; j++) o2[j] = add2(o2[j], pri2[k][j]);
    {
        float s0 = rs8p(o2, r);
        ag8p(s0, r, o2);
    }

    // iterations 0,1: Z cancels; o2 carries the unnormalized weighted sum
    #pragma unroll
    for (int it = 0; it < 2; it++) {
        ull t = mul2(o2[0], o2[0]);
        t = fma2(o2[1], o2[1], t);
        t = fma2(o2[2], o2[2], t);
        t = fma2(o2[3], o2[3], t);
        float ta, tb; unpack2(t, ta, tb);
        float inv = rsqrtf(fmaxf(ta + tb, 1e-24f));

        float e[CNT];
        #pragma unroll
        for (int k = 0; k < CNT; k++) {
            ull s = mul2(pri2[k][0], o2[0]);
            s = fma2(pri2[k][1], o2[1], s);
            s = fma2(pri2[k][2], o2[2], s);
            s = fma2(pri2[k][3], o2[3], s);
            float sa, sb; unpack2(s, sa, sb);
            e[k] = __expf((sa + sb) * inv);
        }

        ull acc2[4];
        {
            ull e2 = pack2(e[0], e[0]);
            #pragma unroll
            for (int j = 0; j < 4; j++) acc2[j] = mul2(e2, pri2[0][j]);
        }
        #pragma unroll
        for (int k = 1; k < CNT; k++) {
            ull e2 = pack2(e[k], e[k]);
            #pragma unroll
            for (int j = 0; j < 4; j++) acc2[j] = fma2(e2, pri2[k][j], acc2[j]);
        }

        float s = rs8p(acc2, r);
        ag8p(s, r, o2);
    }

    // final iteration: true magnitude needed -> compute Z
    {
        ull t = mul2(o2[0], o2[0]);
        t = fma2(o2[1], o2[1], t);
        t = fma2(o2[2], o2[2], t);
        t = fma2(o2[3], o2[3], t);
        float ta, tb; unpack2(t, ta, tb);
        float inv = rsqrtf(fmaxf(ta + tb, 1e-24f));

        float e[CNT];
        float z = 0.f;
        #pragma unroll
        for (int k = 0; k < CNT; k++) {
            ull s = mul2(pri2[k][0], o2[0]);
            s = fma2(pri2[k][1], o2[1], s);
            s = fma2(pri2[k][2], o2[2], s);
            s = fma2(pri2[k][3], o2[3], s);
            float sa, sb; unpack2(s, sa, sb);
            e[k] = __expf((sa + sb) * inv);
            z += e[k];
        }
        z += __shfl_xor_sync(FULL, z, 1, 8);
        z += __shfl_xor_sync(FULL, z, 2, 8);
        z += __shfl_xor_sync(FULL, z, 4, 8);
        z += NZEROS;

        ull acc2[4];
        {
            ull e2 = pack2(e[0], e[0]);
            #pragma unroll
            for (int j = 0; j < 4; j++) acc2[j] = mul2(e2, pri2[0][j]);
        }
        #pragma unroll
        for (int k = 1; k < CNT; k++) {
            ull e2 = pack2(e[k], e[k]);
            #pragma unroll
            for (int j = 0; j < 4; j++) acc2[j] = fma2(e2, pri2[k][j], acc2[j]);
        }

        float s   = rs8p(acc2, r);
        float orr = s * __fdividef(1.0f, z);

        float sq = orr * orr;
        sq += __shfl_xor_sync(FULL, sq, 1, 8);
        sq += __shfl_xor_sync(FULL, sq, 2, 8);
        sq += __shfl_xor_sync(FULL, sq, 4, 8);

        float scale = sq / ((1.0f + sq) * sqrtf(sq + 1e-12f));
        y[((n * 64 + ch) * 64 + p) * 64 + q] = orr * scale + bs[ch];
    }
}

// one pixel for one 64-thread group; xs = lane's x base in smem,
// wrow = lane's packed weight row in smem.
template<int NTAP>
__device__ __forceinline__ void caps_pixel(
    const float* __restrict__ xs, const float* __restrict__ wrow,
    int n, int p, int q, int ch, int r,
    const float* __restrict__ bs, float* __restrict__ y)
{
    constexpr int FSTRIDE = (8 / NTAP) * 76;   // x offset per owned prior k

    ull pri2[NTAP][4];
    #pragma unroll
    for (int k = 0; k < NTAP; k++)
        #pragma unroll
        for (int j = 0; j < 4; j++) pri2[k][j] = 0ull;

    #pragma unroll
    for (int l = 0; l < 8; l++) {
        const ulonglong2* wp = (const ulonglong2*)(wrow + l * (64 * NTAP));
        ulonglong2 wa = wp[0];            // (m0,m1),(m2,m3)
        ulonglong2 wb = wp[1];            // (m4,m5),(m6,m7)
        #pragma unroll
        for (int k = 0; k < NTAP; k++) {
            float xv = xs[k * FSTRIDE + l * 8];
            ull xx = pack2(xv, xv);
            pri2[k][0] = fma2(xx, wa.x, pri2[k][0]);
            pri2[k][1] = fma2(xx, wa.y, pri2[k][1]);
            pri2[k][2] = fma2(xx, wb.x, pri2[k][2]);
            pri2[k][3] = fma2(xx, wb.y, pri2[k][3]);
        }
    }

    route_and_store<NTAP>(pri2, n, p, q, ch, r, bs, y);
}

__global__ __launch_bounds__(512, 2)
void caps_kernel(const float* __restrict__ x,
                 const float* __restrict__ wt,
                 const float* __restrict__ bs,
                 float* __restrict__ y)
{
    __shared__ __align__(16) float s_x[2 * 610];   // [a][f0*76 + l*8 + jj]
    __shared__ __align__(16) float s_w[3072];      // slab A then slab B

    const int bid = blockIdx.x;
    const int q0  = (bid & 7) << 3;
    const int p   = (bid >> 3) & 63;
    const int n   = bid >> 9;
    const int tid = threadIdx.x;

    const int podd = p & 1;

    // ---- stage x: thread (c, jj) -> s_x[a*610 + (c>>3)*76 + (c&7)*8 + jj] ----
    {
        const int c  = tid >> 3;
        const int jj = tid & 7;
        const int j  = (q0 >> 1) + jj;
        const int i0 = p >> 1;                 // p even: p/2; p odd: (p-1)/2
        const int rows = 1 + podd;
        const int dst = (c >> 3) * 76 + (c & 7) * 8 + jj;
        #pragma unroll
        for (int a = 0; a < 2; a++) {
            if (a < rows) {
                int i = i0 + a;
                float v = (i < 32 && j < 32)
                        ? x[((n * 64 + c) * 32 + i) * 32 + j] : 0.f;
                s_x[a * 610 + dst] = v;
            }
        }
    }

    // ---- stage packed weights: slab A (q even class), slab B (q odd class) ----
    // A: p even -> EE (ntap 1); p odd -> OE (ntap 2)
    // B: p even -> EO (ntap 2); p odd -> OO (ntap 4)
    const int ntapA = podd ? 2 : 1;
    const int ntapB = podd ? 4 : 2;
    const int shA   = podd ? 1 : 0;     // log2(ntapA)
    const int shB   = podd ? 2 : 1;
    const int szA   = 512 * ntapA;
    {
        const int total = szA + 512 * ntapB;
        for (int idx = tid; idx < total; idx += 512) {
            bool inB = idx >= szA;
            int e  = inB ? idx - szA : idx;
            int sh = inB ? shB : shA;
            int m  = e & 7;
            int et = e >> 3;
            int t  = et & ((1 << sh) - 1);
            int lg = et >> sh;               // l*8 + g
            int kh, kw;
            if (!podd) { kh = 1; kw = inB ? (t << 1) : 1; }
            else if (!inB) { kh = t << 1; kw = 1; }
            else { kh = (t >> 1) << 1; kw = (t & 1) << 1; }
            int woff = (2 - kh) * 3 + (2 - kw);     // flipped kernel tap
            s_w[idx] = wt[lg * 72 + m * 9 + woff];
        }
    }
    __syncthreads();

    // ---- pixel groups: gi = tid>>6 owns q = q0 + gi ----
    const int gi  = tid >> 6;
    const int t64 = tid & 63;
    const int g   = t64 >> 3;
    const int r   = t64 & 7;
    const int q   = q0 + gi;
    const int jjb = gi >> 1;     // (q - q0)/2 for even q; (q-1-q0)/2 for odd q

    if (!podd) {
        if ((gi & 1) == 0) {     // EE: NTAP=1, a=0, f0=r, jj=jjb
            const float* xs = s_x + r * 76 + jjb;
            const float* wrow = s_w + g * 8;
            caps_pixel<1>(xs, wrow, n, p, q, t64, r, bs, y);
        } else {                 // EO: NTAP=2, a=0, tp varies j
            int tp = r & 1, f0 = r >> 1;
            const float* xs = s_x + f0 * 76 + jjb + tp;
            const float* wrow = s_w + szA + (g * 2 + tp) * 8;
            caps_pixel<2>(xs, wrow, n, p, q, t64, r, bs, y);
        }
    } else {
        if ((gi & 1) == 0) {     // OE: NTAP=2, tp varies i (a = tp)
            int tp = r & 1, f0 = r >> 1;
            const float* xs = s_x + tp * 610 + f0 * 76 + jjb;
            const float* wrow = s_w + (g * 2 + tp) * 8;
            caps_pixel<2>(xs, wrow, n, p, q, t64, r, bs, y);
        } else {                 // OO: NTAP=4, a = tp>>1, jj += tp&1
            int tp = r & 3, f0 = r >> 2;
            const float* xs = s_x + (tp >> 1) * 610 + f0 * 76 + jjb + (tp & 1);
            const float* wrow = s_w + szA + (g * 4 + tp) * 8;
            caps_pixel<4>(xs, wrow, n, p, q, t64, r, bs, y);
        }
    }
}

extern "C" void kernel_launch(void* const* d_in, const int* in_sizes, int n_in,
                              void* d_out, int out_size) {
    const float* x  = (const float*)d_in[0];
    const float* wt = (const float*)d_in[1];
    const float* bs = (const float*)d_in[2];
    float* y = (float*)d_out;
    caps_kernel<<<1024, 512>>>(x, wt, bs, y);
}

// round 12
// speedup vs baseline: 1.1342x; 1.1342x over previous
#include <cuda_runtime.h>

// CapsuleConvTranspose2d (2,64,32,32) -> (2,64,64,64): stride-2 3x3 transposed
// conv into 8 out-capsules x 8 dims, 3-iter k-means routing, squash, bias.
//
// patch[n,c,kh,kw,p,q] = x[n,c,(p+kh-1)/2,(q+kw-1)/2] iff (p+kh-1) even & in
// range, else 0. Valid kh depends only on parity of p (even->{1}, odd->{0,2});
// same for q/kw. Border taps (p or q = 63, tap 2) zero-filled: a zero prior
// routes identically (exp(0)=1 in Z), counted in NZEROS.
//
// Routing algebra: iterations only consume out/||out||, and out = acc/Z, so Z
// cancels in iterations 0..1 (and the init's 1/72). Z is computed only in the
// final iteration where the magnitude feeds squash. Softmax without max
// subtraction (logits O(1), fp32-safe); zero priors add exactly NZEROS to Z.
//
// Vector math is packed f32x2 (SASS FFMA2 via PTX fma.rn.f32x2); width-8
// cross-lane reductions use packed reduce-scatter (7 wavefronts) + all-gather.
//
// Kernel 1 (tiny prep): pack weights per parity class into global g_wpk
// [cls][(l*8+g)*ntap+tp][m], flipped taps baked in. One element per thread.
// Kernel 2 (fused main): block = 256 threads = one (n,p) row x 4 consecutive
// q. x staged in-block from the RAW input layout (coalesced), smem layout
// [a*610 + f0*76 + l*8 + jj] (bank-conflict-free reads for all 4 classes).
// Weights read directly from g_wpk (L1-resident broadcast LDG.128).

typedef unsigned long long ull;

__device__ __forceinline__ ull pack2(float lo, float hi) {
    ull r; asm("mov.b64 %0,{%1,%2};" : "=l"(r) : "f"(lo), "f"(hi)); return r;
}
__device__ __forceinline__ void unpack2(ull v, float& lo, float& hi) {
    asm("mov.b64 {%0,%1},%2;" : "=f"(lo), "=f"(hi) : "l"(v));
}
__device__ __forceinline__ ull fma2(ull a, ull b, ull c) {
    ull d; asm("fma.rn.f32x2 %0,%1,%2,%3;" : "=l"(d) : "l"(a), "l"(b), "l"(c)); return d;
}
__device__ __forceinline__ ull mul2(ull a, ull b) {
    ull d; asm("mul.rn.f32x2 %0,%1,%2;" : "=l"(d) : "l"(a), "l"(b)); return d;
}
__device__ __forceinline__ ull add2(ull a, ull b) {
    ull d; asm("add.rn.f32x2 %0,%1,%2;" : "=l"(d) : "l"(a), "l"(b)); return d;
}

__device__ __align__(16) float g_wpk[4608];   // cls bases: 0,512,1536,2560

__global__ void wpack_kernel(const float* __restrict__ wt)
{
    const int w = blockIdx.x * 256 + threadIdx.x;   // 18*256 = 4608
    int cls, rem, ntap;
    if (w < 512)       { cls = 0; rem = w;        ntap = 1; }
    else if (w < 1536) { cls = 1; rem = w - 512;  ntap = 2; }
    else if (w < 2560) { cls = 2; rem = w - 1536; ntap = 2; }
    else               { cls = 3; rem = w - 2560; ntap = 4; }
    int m  = rem & 7;
    int e  = rem >> 3;          // (l*8+g)*ntap + tp
    int tp = e % ntap;
    int lg = e / ntap;          // l*8 + g
    int kh, kw;
    if (cls == 0)      { kh = 1;              kw = 1; }
    else if (cls == 1) { kh = 1;              kw = tp << 1; }
    else if (cls == 2) { kh = tp << 1;        kw = 1; }
    else               { kh = (tp >> 1) << 1; kw = (tp & 1) << 1; }
    int woff = (2 - kh) * 3 + (2 - kw);       // flipped kernel tap
    g_wpk[w] = wt[(lg * 8 + m) * 9 + woff];
}

// packed reduce-scatter over width 8 -> fully-summed component r on lane r
__device__ __forceinline__ float rs8p(const ull v[4], int r)
{
    const unsigned FULL = 0xffffffffu;
    const bool b4 = (r & 4) != 0, b2 = (r & 2) != 0, b1 = (r & 1) != 0;
    ull s0 = b4 ? v[0] : v[2];
    ull s1 = b4 ? v[1] : v[3];
    ull k0 = b4 ? v[2] : v[0];
    ull k1 = b4 ? v[3] : v[1];
    ull w0 = add2(k0, __shfl_xor_sync(FULL, s0, 4, 8));
    ull w1 = add2(k1, __shfl_xor_sync(FULL, s1, 4, 8));
    ull su = b2 ? w0 : w1;
    ull ku = b2 ? w1 : w0;
    ull u  = add2(ku, __shfl_xor_sync(FULL, su, 2, 8));
    float ua, ub; unpack2(u, ua, ub);
    float sf = b1 ? ua : ub;
    float kf = b1 ? ub : ua;
    return kf + __shfl_xor_sync(FULL, sf, 1, 8);
}

// all-gather over width 8: scalar s (component r on lane r) -> o2[4] packed
__device__ __forceinline__ void ag8p(float s, int r, ull o2[4])
{
    const unsigned FULL = 0xffffffffu;
    const bool b4 = (r & 4) != 0, b2 = (r & 2) != 0, b1 = (r & 1) != 0;
    float t = __shfl_xor_sync(FULL, s, 1, 8);
    float lo = b1 ? t : s;
    float hi = b1 ? s : t;
    ull u  = pack2(lo, hi);
    ull t2 = __shfl_xor_sync(FULL, u, 2, 8);
    ull w0 = b2 ? t2 : u;
    ull w1 = b2 ? u : t2;
    ull t0 = __shfl_xor_sync(FULL, w0, 4, 8);
    ull t1 = __shfl_xor_sync(FULL, w1, 4, 8);
    o2[0] = b4 ? t0 : w0;
    o2[1] = b4 ? t1 : w1;
    o2[2] = b4 ? w0 : t0;
    o2[3] = b4 ? w1 : t1;
}

// routing + squash + store; priors packed: pri2[k][j] = (m=2j, m=2j+1)
template<int CNT>
__device__ __forceinline__ void route_and_store(
    ull pri2[CNT][4], int n, int p, int q, int ch, int r,
    const float* __restrict__ bs, float* __restrict__ y)
{
    constexpr float NZEROS = (float)(72 - 8 * CNT);
    const unsigned FULL = 0xffffffffu;

    // init: out0 direction = sum of priors (1/72 cancels)
    ull o2[4];
    #pragma unroll
    for (int j = 0; j < 4; j++) o2[j] = pri2[0][j];
    #pragma unroll
    for (int k = 1; k < CNT; k++)
        #pragma unroll
        for (int j = 0; j < 4; j++) o2[j] = add2(o2[j], pri2[k][j]);
    {
        float s0 = rs8p(o2, r);
        ag8p(s0, r, o2);
    }

    // iterations 0,1: Z cancels; o2 carries the unnormalized weighted sum
    #pragma unroll
    for (int it = 0; it < 2; it++) {
        ull t = mul2(o2[0], o2[0]);
        t = fma2(o2[1], o2[1], t);
        t = fma2(o2[2], o2[2], t);
        t = fma2(o2[3], o2[3], t);
        float ta, tb; unpack2(t, ta, tb);
        float inv = rsqrtf(fmaxf(ta + tb, 1e-24f));

        float e[CNT];
        #pragma unroll
        for (int k = 0; k < CNT; k++) {
            ull s = mul2(pri2[k][0], o2[0]);
            s = fma2(pri2[k][1], o2[1], s);
            s = fma2(pri2[k][2], o2[2], s);
            s = fma2(pri2[k][3], o2[3], s);
            float sa, sb; unpack2(s, sa, sb);
            e[k] = __expf((sa + sb) * inv);
        }

        ull acc2[4];
        {
            ull e2 = pack2(e[0], e[0]);
            #pragma unroll
            for (int j = 0; j < 4; j++) acc2[j] = mul2(e2, pri2[0][j]);
        }
        #pragma unroll
        for (int k = 1; k < CNT; k++) {
            ull e2 = pack2(e[k], e[k]);
            #pragma unroll
            for (int j = 0; j < 4; j++) acc2[j] = fma2(e2, pri2[k][j], acc2[j]);
        }

        float s = rs8p(acc2, r);
        ag8p(s, r, o2);
    }

    // final iteration: true magnitude needed -> compute Z
    {
        ull t = mul2(o2[0], o2[0]);
        t = fma2(o2[1], o2[1], t);
        t = fma2(o2[2], o2[2], t);
        t = fma2(o2[3], o2[3], t);
        float ta, tb; unpack2(t, ta, tb);
        float inv = rsqrtf(fmaxf(ta + tb, 1e-24f));

        float e[CNT];
        float z = 0.f;
        #pragma unroll
        for (int k = 0; k < CNT; k++) {
            ull s = mul2(pri2[k][0], o2[0]);
            s = fma2(pri2[k][1], o2[1], s);
            s = fma2(pri2[k][2], o2[2], s);
            s = fma2(pri2[k][3], o2[3], s);
            float sa, sb; unpack2(s, sa, sb);
            e[k] = __expf((sa + sb) * inv);
            z += e[k];
        }
        z += __shfl_xor_sync(FULL, z, 1, 8);
        z += __shfl_xor_sync(FULL, z, 2, 8);
        z += __shfl_xor_sync(FULL, z, 4, 8);
        z += NZEROS;

        ull acc2[4];
        {
            ull e2 = pack2(e[0], e[0]);
            #pragma unroll
            for (int j = 0; j < 4; j++) acc2[j] = mul2(e2, pri2[0][j]);
        }
        #pragma unroll
        for (int k = 1; k < CNT; k++) {
            ull e2 = pack2(e[k], e[k]);
            #pragma unroll
            for (int j = 0; j < 4; j++) acc2[j] = fma2(e2, pri2[k][j], acc2[j]);
        }

        float s   = rs8p(acc2, r);
        float orr = s * __fdividef(1.0f, z);

        float sq = orr * orr;
        sq += __shfl_xor_sync(FULL, sq, 1, 8);
        sq += __shfl_xor_sync(FULL, sq, 2, 8);
        sq += __shfl_xor_sync(FULL, sq, 4, 8);

        float scale = sq / ((1.0f + sq) * sqrtf(sq + 1e-12f));
        y[((n * 64 + ch) * 64 + p) * 64 + q] = orr * scale + bs[ch];
    }
}

// one pixel for one 64-thread group; xs = lane's x base in smem,
// wrow = lane's packed weight row in g_wpk.
template<int NTAP>
__device__ __forceinline__ void caps_pixel(
    const float* __restrict__ xs, const float* __restrict__ wrow,
    int n, int p, int q, int ch, int r,
    const float* __restrict__ bs, float* __restrict__ y)
{
    constexpr int FSTRIDE = (8 / NTAP) * 76;   // x offset per owned prior k

    ull pri2[NTAP][4];
    #pragma unroll
    for (int k = 0; k < NTAP; k++)
        #pragma unroll
        for (int j = 0; j < 4; j++) pri2[k][j] = 0ull;

    #pragma unroll
    for (int l = 0; l < 8; l++) {
        const ulonglong2* wp = (const ulonglong2*)(wrow + l * (64 * NTAP));
        ulonglong2 wa = wp[0];            // (m0,m1),(m2,m3)
        ulonglong2 wb = wp[1];            // (m4,m5),(m6,m7)
        #pragma unroll
        for (int k = 0; k < NTAP; k++) {
            float xv = xs[k * FSTRIDE + l * 8];
            ull xx = pack2(xv, xv);
            pri2[k][0] = fma2(xx, wa.x, pri2[k][0]);
            pri2[k][1] = fma2(xx, wa.y, pri2[k][1]);
            pri2[k][2] = fma2(xx, wb.x, pri2[k][2]);
            pri2[k][3] = fma2(xx, wb.y, pri2[k][3]);
        }
    }

    route_and_store<NTAP>(pri2, n, p, q, ch, r, bs, y);
}

__global__ __launch_bounds__(256, 4)
void caps_kernel(const float* __restrict__ x,
                 const float* __restrict__ bs,
                 float* __restrict__ y)
{
    __shared__ __align__(16) float s_x[2 * 610];   // [a][f0*76 + l*8 + jj]

    const int bid = blockIdx.x;
    const int q0  = (bid & 15) << 2;
    const int p   = (bid >> 4) & 63;
    const int n   = bid >> 10;
    const int tid = threadIdx.x;

    const int podd = p & 1;

    // ---- stage x: thread (c, jj) -> s_x[a*610 + (c>>3)*76 + (c&7)*8 + jj] ----
    {
        const int c  = tid >> 2;
        const int jj = tid & 3;
        const int j  = (q0 >> 1) + jj;
        const int i0 = p >> 1;                 // p even: p/2; p odd: (p-1)/2
        const int rows = 1 + podd;
        const int dst = (c >> 3) * 76 + (c & 7) * 8 + jj;
        #pragma unroll
        for (int a = 0; a < 2; a++) {
            if (a < rows) {
                int i = i0 + a;
                float v = (i < 32 && j < 32)
                        ? x[((n * 64 + c) * 32 + i) * 32 + j] : 0.f;
                s_x[a * 610 + dst] = v;
            }
        }
    }
    __syncthreads();

    // ---- pixel groups: gi = tid>>6 owns q = q0 + gi ----
    const int gi  = tid >> 6;
    const int t64 = tid & 63;
    const int g   = t64 >> 3;
    const int r   = t64 & 7;
    const int q   = q0 + gi;
    const int jjb = gi >> 1;     // (q-q0)/2 for even q; (q-1-q0)/2 for odd q

    if (!podd) {
        if ((gi & 1) == 0) {     // EE: NTAP=1, a=0, f0=r, jj=jjb
            const float* xs = s_x + r * 76 + jjb;
            const float* wrow = g_wpk + g * 8;
            caps_pixel<1>(xs, wrow, n, p, q, t64, r, bs, y);
        } else {                 // EO: NTAP=2, a=0, tp varies j
            int tp = r & 1, f0 = r >> 1;
            const float* xs = s_x + f0 * 76 + jjb + tp;
            const float* wrow = g_wpk + 512 + (g * 2 + tp) * 8;
            caps_pixel<2>(xs, wrow, n, p, q, t64, r, bs, y);
        }
    } else {
        if ((gi & 1) == 0) {     // OE: NTAP=2, tp varies i (a = tp)
            int tp = r & 1, f0 = r >> 1;
            const float* xs = s_x + tp * 610 + f0 * 76 + jjb;
            const float* wrow = g_wpk + 1536 + (g * 2 + tp) * 8;
            caps_pixel<2>(xs, wrow, n, p, q, t64, r, bs, y);
        } else {                 // OO: NTAP=4, a = tp>>1, jj += tp&1
            int tp = r & 3, f0 = r >> 2;
            const float* xs = s_x + (tp >> 1) * 610 + f0 * 76 + jjb + (tp & 1);
            const float* wrow = g_wpk + 2560 + (g * 4 + tp) * 8;
            caps_pixel<4>(xs, wrow, n, p, q, t64, r, bs, y);
        }
    }
}

extern "C" void kernel_launch(void* const* d_in, const int* in_sizes, int n_in,
                              void* d_out, int out_size) {
    const float* x  = (const float*)d_in[0];
    const float* wt = (const float*)d_in[1];
    const float* bs = (const float*)d_in[2];
    float* y = (float*)d_out;
    wpack_kernel<<<18, 256>>>(wt);
    caps_kernel<<<2 * 64 * 16, 256>>>(x, bs, y);
}

// round 13
// speedup vs baseline: 1.1463x; 1.0107x over previous
#include <cuda_runtime.h>

// CapsuleConvTranspose2d (2,64,32,32) -> (2,64,64,64): stride-2 3x3 transposed
// conv into 8 out-capsules x 8 dims, 3-iter k-means routing, squash, bias.
//
// patch[n,c,kh,kw,p,q] = x[n,c,(p+kh-1)/2,(q+kw-1)/2] iff (p+kh-1) even & in
// range, else 0. Valid kh depends only on parity of p (even->{1}, odd->{0,2});
// same for q/kw. Border taps (p or q = 63, tap 2) zero-filled: a zero prior
// routes identically (exp(0)=1 in Z), counted in NZEROS.
//
// Routing algebra: iterations only consume out/||out||, and out = acc/Z, so Z
// cancels in iterations 0..1 (and the init's 1/72). Z is computed only in the
// final iteration where the magnitude feeds squash. Softmax without max
// subtraction (logits O(1), fp32-safe); zero priors add exactly NZEROS to Z.
//
// Vector math is packed f32x2 (SASS FFMA2 via PTX fma.rn.f32x2); width-8
// cross-lane reductions use packed reduce-scatter (7 wavefronts) + all-gather.
//
// Kernel 1 (tiny prep): pack weights per parity class into global g_wpk.
// Kernel 2 (fused main): block = 256 threads = one (n,p) row x 4 consecutive
// q; x staged in-block (coalesced), weights read from g_wpk (L1-resident
// LDG.128). Launched with PROGRAMMATIC STREAM SERIALIZATION: caps overlaps
// wpack's tail; it calls cudaGridDependencySynchronize() after x staging,
// just before the first g_wpk read.

typedef unsigned long long ull;

__device__ __forceinline__ ull pack2(float lo, float hi) {
    ull r; asm("mov.b64 %0,{%1,%2};" : "=l"(r) : "f"(lo), "f"(hi)); return r;
}
__device__ __forceinline__ void unpack2(ull v, float& lo, float& hi) {
    asm("mov.b64 {%0,%1},%2;" : "=f"(lo), "=f"(hi) : "l"(v));
}
__device__ __forceinline__ ull fma2(ull a, ull b, ull c) {
    ull d; asm("fma.rn.f32x2 %0,%1,%2,%3;" : "=l"(d) : "l"(a), "l"(b), "l"(c)); return d;
}
__device__ __forceinline__ ull mul2(ull a, ull b) {
    ull d; asm("mul.rn.f32x2 %0,%1,%2;" : "=l"(d) : "l"(a), "l"(b)); return d;
}
__device__ __forceinline__ ull add2(ull a, ull b) {
    ull d; asm("add.rn.f32x2 %0,%1,%2;" : "=l"(d) : "l"(a), "l"(b)); return d;
}

__device__ __align__(16) float g_wpk[4608];   // cls bases: 0,512,1536,2560

__global__ void wpack_kernel(const float* __restrict__ wt)
{
    const int w = blockIdx.x * 256 + threadIdx.x;   // 18*256 = 4608
    int cls, rem, ntap;
    if (w < 512)       { cls = 0; rem = w;        ntap = 1; }
    else if (w < 1536) { cls = 1; rem = w - 512;  ntap = 2; }
    else if (w < 2560) { cls = 2; rem = w - 1536; ntap = 2; }
    else               { cls = 3; rem = w - 2560; ntap = 4; }
    int m  = rem & 7;
    int e  = rem >> 3;          // (l*8+g)*ntap + tp
    int tp = e % ntap;
    int lg = e / ntap;          // l*8 + g
    int kh, kw;
    if (cls == 0)      { kh = 1;              kw = 1; }
    else if (cls == 1) { kh = 1;              kw = tp << 1; }
    else if (cls == 2) { kh = tp << 1;        kw = 1; }
    else               { kh = (tp >> 1) << 1; kw = (tp & 1) << 1; }
    int woff = (2 - kh) * 3 + (2 - kw);       // flipped kernel tap
    g_wpk[w] = wt[(lg * 8 + m) * 9 + woff];
}

// packed reduce-scatter over width 8 -> fully-summed component r on lane r
__device__ __forceinline__ float rs8p(const ull v[4], int r)
{
    const unsigned FULL = 0xffffffffu;
    const bool b4 = (r & 4) != 0, b2 = (r & 2) != 0, b1 = (r & 1) != 0;
    ull s0 = b4 ? v[0] : v[2];
    ull s1 = b4 ? v[1] : v[3];
    ull k0 = b4 ? v[2] : v[0];
    ull k1 = b4 ? v[3] : v[1];
    ull w0 = add2(k0, __shfl_xor_sync(FULL, s0, 4, 8));
    ull w1 = add2(k1, __shfl_xor_sync(FULL, s1, 4, 8));
    ull su = b2 ? w0 : w1;
    ull ku = b2 ? w1 : w0;
    ull u  = add2(ku, __shfl_xor_sync(FULL, su, 2, 8));
    float ua, ub; unpack2(u, ua, ub);
    float sf = b1 ? ua : ub;
    float kf = b1 ? ub : ua;
    return kf + __shfl_xor_sync(FULL, sf, 1, 8);
}

// all-gather over width 8: scalar s (component r on lane r) -> o2[4] packed
__device__ __forceinline__ void ag8p(float s, int r, ull o2[4])
{
    const unsigned FULL = 0xffffffffu;
    const bool b4 = (r & 4) != 0, b2 = (r & 2) != 0, b1 = (r & 1) != 0;
    float t = __shfl_xor_sync(FULL, s, 1, 8);
    float lo = b1 ? t : s;
    float hi = b1 ? s : t;
    ull u  = pack2(lo, hi);
    ull t2 = __shfl_xor_sync(FULL, u, 2, 8);
    ull w0 = b2 ? t2 : u;
    ull w1 = b2 ? u : t2;
    ull t0 = __shfl_xor_sync(FULL, w0, 4, 8);
    ull t1 = __shfl_xor_sync(FULL, w1, 4, 8);
    o2[0] = b4 ? t0 : w0;
    o2[1] = b4 ? t1 : w1;
    o2[2] = b4 ? w0 : t0;
    o2[3] = b4 ? w1 : t1;
}

// routing + squash + store; priors packed: pri2[k][j] = (m=2j, m=2j+1)
template<int CNT>
__device__ __forceinline__ void route_and_store(
    ull pri2[CNT][4], int n, int p, int q, int ch, int r,
    const float* __restrict__ bs, float* __restrict__ y)
{
    constexpr float NZEROS = (float)(72 - 8 * CNT);
    const unsigned FULL = 0xffffffffu;

    const float bsv = __ldg(&bs[ch]);   // hoisted above the routing chain

    // init: out0 direction = sum of priors (1/72 cancels)
    ull o2[4];
    #pragma unroll
    for (int j = 0; j < 4; j++) o2[j] = pri2[0][j];
    #pragma unroll
    for (int k = 1; k < CNT; k++)
        #pragma unroll
        for (int j = 0; j < 4; j++) o2[j] = add2(o2[j], pri2[k][j]);
    {
        float s0 = rs8p(o2, r);
        ag8p(s0, r, o2);
    }

    // iterations 0,1: Z cancels; o2 carries the unnormalized weighted sum
    #pragma unroll
    for (int it = 0; it < 2; it++) {
        ull t = mul2(o2[0], o2[0]);
        t = fma2(o2[1], o2[1], t);
        t = fma2(o2[2], o2[2], t);
        t = fma2(o2[3], o2[3], t);
        float ta, tb; unpack2(t, ta, tb);
        float inv = rsqrtf(fmaxf(ta + tb, 1e-24f));

        float e[CNT];
        #pragma unroll
        for (int k = 0; k < CNT; k++) {
            ull s = mul2(pri2[k][0], o2[0]);
            s = fma2(pri2[k][1], o2[1], s);
            s = fma2(pri2[k][2], o2[2], s);
            s = fma2(pri2[k][3], o2[3], s);
            float sa, sb; unpack2(s, sa, sb);
            e[k] = __expf((sa + sb) * inv);
        }

        ull acc2[4];
        {
            ull e2 = pack2(e[0], e[0]);
            #pragma unroll
            for (int j = 0; j < 4; j++) acc2[j] = mul2(e2, pri2[0][j]);
        }
        #pragma unroll
        for (int k = 1; k < CNT; k++) {
            ull e2 = pack2(e[k], e[k]);
            #pragma unroll
            for (int j = 0; j < 4; j++) acc2[j] = fma2(e2, pri2[k][j], acc2[j]);
        }

        float s = rs8p(acc2, r);
        ag8p(s, r, o2);
    }

    // final iteration: true magnitude needed -> compute Z
    {
        ull t = mul2(o2[0], o2[0]);
        t = fma2(o2[1], o2[1], t);
        t = fma2(o2[2], o2[2], t);
        t = fma2(o2[3], o2[3], t);
        float ta, tb; unpack2(t, ta, tb);
        float inv = rsqrtf(fmaxf(ta + tb, 1e-24f));

        float e[CNT];
        float z = 0.f;
        #pragma unroll
        for (int k = 0; k < CNT; k++) {
            ull s = mul2(pri2[k][0], o2[0]);
            s = fma2(pri2[k][1], o2[1], s);
            s = fma2(pri2[k][2], o2[2], s);
            s = fma2(pri2[k][3], o2[3], s);
            float sa, sb; unpack2(s, sa, sb);
            e[k] = __expf((sa + sb) * inv);
            z += e[k];
        }
        z += __shfl_xor_sync(FULL, z, 1, 8);
        z += __shfl_xor_sync(FULL, z, 2, 8);
        z += __shfl_xor_sync(FULL, z, 4, 8);
        z += NZEROS;

        ull acc2[4];
        {
            ull e2 = pack2(e[0], e[0]);
            #pragma unroll
            for (int j = 0; j < 4; j++) acc2[j] = mul2(e2, pri2[0][j]);
        }
        #pragma unroll
        for (int k = 1; k < CNT; k++) {
            ull e2 = pack2(e[k], e[k]);
            #pragma unroll
            for (int j = 0; j < 4; j++) acc2[j] = fma2(e2, pri2[k][j], acc2[j]);
        }

        float s   = rs8p(acc2, r);
        float orr = s * __fdividef(1.0f, z);

        float sq = orr * orr;
        sq += __shfl_xor_sync(FULL, sq, 1, 8);
        sq += __shfl_xor_sync(FULL, sq, 2, 8);
        sq += __shfl_xor_sync(FULL, sq, 4, 8);

        float scale = sq / ((1.0f + sq) * sqrtf(sq + 1e-12f));
        y[((n * 64 + ch) * 64 + p) * 64 + q] = orr * scale + bsv;
    }
}

// one pixel for one 64-thread group; xs = lane's x base in smem,
// wrow = lane's packed weight row in g_wpk.
template<int NTAP>
__device__ __forceinline__ void caps_pixel(
    const float* __restrict__ xs, const float* __restrict__ wrow,
    int n, int p, int q, int ch, int r,
    const float* __restrict__ bs, float* __restrict__ y)
{
    constexpr int FSTRIDE = (8 / NTAP) * 76;   // x offset per owned prior k

    ull pri2[NTAP][4];
    #pragma unroll
    for (int k = 0; k < NTAP; k++)
        #pragma unroll
        for (int j = 0; j < 4; j++) pri2[k][j] = 0ull;

    #pragma unroll
    for (int l = 0; l < 8; l++) {
        const ulonglong2* wp = (const ulonglong2*)(wrow + l * (64 * NTAP));
        ulonglong2 wa = wp[0];            // (m0,m1),(m2,m3)
        ulonglong2 wb = wp[1];            // (m4,m5),(m6,m7)
        #pragma unroll
        for (int k = 0; k < NTAP; k++) {
            float xv = xs[k * FSTRIDE + l * 8];
            ull xx = pack2(xv, xv);
            pri2[k][0] = fma2(xx, wa.x, pri2[k][0]);
            pri2[k][1] = fma2(xx, wa.y, pri2[k][1]);
            pri2[k][2] = fma2(xx, wb.x, pri2[k][2]);
            pri2[k][3] = fma2(xx, wb.y, pri2[k][3]);
        }
    }

    route_and_store<NTAP>(pri2, n, p, q, ch, r, bs, y);
}

__global__ __launch_bounds__(256, 4)
void caps_kernel(const float* __restrict__ x,
                 const float* __restrict__ bs,
                 float* __restrict__ y)
{
    __shared__ __align__(16) float s_x[2 * 610];   // [a][f0*76 + l*8 + jj]

    const int bid = blockIdx.x;
    const int q0  = (bid & 15) << 2;
    const int p   = (bid >> 4) & 63;
    const int n   = bid >> 10;
    const int tid = threadIdx.x;

    const int podd = p & 1;

    // ---- stage x: thread (c, jj) -> s_x[a*610 + (c>>3)*76 + (c&7)*8 + jj] ----
    {
        const int c  = tid >> 2;
        const int jj = tid & 3;
        const int j  = (q0 >> 1) + jj;
        const int i0 = p >> 1;                 // p even: p/2; p odd: (p-1)/2
        const int rows = 1 + podd;
        const int dst = (c >> 3) * 76 + (c & 7) * 8 + jj;
        #pragma unroll
        for (int a = 0; a < 2; a++) {
            if (a < rows) {
                int i = i0 + a;
                float v = (i < 32 && j < 32)
                        ? x[((n * 64 + c) * 32 + i) * 32 + j] : 0.f;
                s_x[a * 610 + dst] = v;
            }
        }
    }
    __syncthreads();

    // PDL: wait for wpack's g_wpk writes (overlapped with the staging above)
    cudaGridDependencySynchronize();

    // ---- pixel groups: gi = tid>>6 owns q = q0 + gi ----
    const int gi  = tid >> 6;
    const int t64 = tid & 63;
    const int g   = t64 >> 3;
    const int r   = t64 & 7;
    const int q   = q0 + gi;
    const int jjb = gi >> 1;     // (q-q0)/2 for even q; (q-1-q0)/2 for odd q

    if (!podd) {
        if ((gi & 1) == 0) {     // EE: NTAP=1, a=0, f0=r, jj=jjb
            const float* xs = s_x + r * 76 + jjb;
            const float* wrow = g_wpk + g * 8;
            caps_pixel<1>(xs, wrow, n, p, q, t64, r, bs, y);
        } else {                 // EO: NTAP=2, a=0, tp varies j
            int tp = r & 1, f0 = r >> 1;
            const float* xs = s_x + f0 * 76 + jjb + tp;
            const float* wrow = g_wpk + 512 + (g * 2 + tp) * 8;
            caps_pixel<2>(xs, wrow, n, p, q, t64, r, bs, y);
        }
    } else {
        if ((gi & 1) == 0) {     // OE: NTAP=2, tp varies i (a = tp)
            int tp = r & 1, f0 = r >> 1;
            const float* xs = s_x + tp * 610 + f0 * 76 + jjb;
            const float* wrow = g_wpk + 1536 + (g * 2 + tp) * 8;
            caps_pixel<2>(xs, wrow, n, p, q, t64, r, bs, y);
        } else {                 // OO: NTAP=4, a = tp>>1, jj += tp&1
            int tp = r & 3, f0 = r >> 2;
            const float* xs = s_x + (tp >> 1) * 610 + f0 * 76 + jjb + (tp & 1);
            const float* wrow = g_wpk + 2560 + (g * 4 + tp) * 8;
            caps_pixel<4>(xs, wrow, n, p, q, t64, r, bs, y);
        }
    }
}

extern "C" void kernel_launch(void* const* d_in, const int* in_sizes, int n_in,
                              void* d_out, int out_size) {
    const float* x  = (const float*)d_in[0];
    const float* wt = (const float*)d_in[1];
    const float* bs = (const float*)d_in[2];
    float* y = (float*)d_out;

    wpack_kernel<<<18, 256>>>(wt);

    // Launch caps with programmatic stream serialization: its launch + x
    // staging overlap wpack's tail; cudaGridDependencySynchronize() inside
    // the kernel enforces the g_wpk dependency.
    cudaLaunchConfig_t cfg = {};
    cfg.gridDim  = dim3(2 * 64 * 16, 1, 1);
    cfg.blockDim = dim3(256, 1, 1);
    cudaLaunchAttribute attrs[1];
    attrs[0].id = cudaLaunchAttributeProgrammaticStreamSerialization;
    attrs[0].val.programmaticStreamSerializationAllowed = 1;
    cfg.attrs = attrs;
    cfg.numAttrs = 1;
    cudaLaunchKernelEx(&cfg, caps_kernel, x, bs, y);
}